// round 8
// baseline (speedup 1.0000x reference)
#include <cuda_runtime.h>
#include <cstdint>

#define NB 4
#define NP 8192
#define ND 512
#define NS1 4096
#define NS2 2048
#define ROWS_PER_B (NP + NS1 + NS2)   /* 14336 */
#define OUTX_ELEMS ((size_t)NB * ROWS_PER_B * ND)
#define TPB 512                        /* 16 warps -> 4 per SMSP       */
#define PPT 16                         /* points per thread            */
#define NCOPY 144                      /* copy CTAs fused into fps     */

/* smem layout (bytes) */
#define OFF_SLOT  0        /* u64 reduction slot          */
#define OFF_CNT   512      /* int ssum, int sxor          */
#define OFF_SX    1024
#define OFF_SY    (OFF_SX + NP * 4)
#define OFF_SZ    (OFF_SY + NP * 4)
#define OFF_KEY   (OFF_SZ + NP * 4)          /* u32[8192] */
#define OFF_SID   (OFF_KEY + NP * 4)         /* u16[8192] */
#define SMEM_TOTAL (OFF_SID + NP * 2)        /* 148480 B  */

__device__ int g_fps_idx[NB * NS1];

/* ---------------- packed f32x2 helpers (proven) -------------------- */
__device__ __forceinline__ unsigned long long f32x2_add(unsigned long long a, unsigned long long b) {
    unsigned long long r;
    asm("add.rn.f32x2 %0, %1, %2;" : "=l"(r) : "l"(a), "l"(b));
    return r;
}
__device__ __forceinline__ unsigned long long f32x2_mul(unsigned long long a, unsigned long long b) {
    unsigned long long r;
    asm("mul.rn.f32x2 %0, %1, %2;" : "=l"(r) : "l"(a), "l"(b));
    return r;
}
__device__ __forceinline__ unsigned long long pack2(float lo, float hi) {
    unsigned long long r;
    asm("mov.b64 %0, {%1, %2};" : "=l"(r) : "f"(lo), "f"(hi));
    return r;
}
__device__ __forceinline__ void unpack2(unsigned long long v, float& lo, float& hi) {
    asm("mov.b64 {%0, %1}, %2;" : "=f"(lo), "=f"(hi) : "l"(v));
}

/* ---------------- Morton helpers ----------------------------------- */
__device__ __forceinline__ unsigned expand10(unsigned v) {
    v &= 0x3FFu;
    v = (v | (v << 16)) & 0x030000FFu;
    v = (v | (v <<  8)) & 0x0300F00Fu;
    v = (v | (v <<  4)) & 0x030C30C3u;
    v = (v | (v <<  2)) & 0x09249249u;
    return v;
}
__device__ __forceinline__ unsigned quant10(float x) {
    float q = (x + 8.0f) * 64.0f;
    q = fminf(fmaxf(q, 0.0f), 1023.0f);
    return (unsigned)q;
}

/* ===================================================================
   Fused kernel.
   blockIdx < NB  : FPS — round-7 algorithm with a shortened per-step
                    reduction tail:
                      * dirty warps: REDUX pair -> cached packed
                        candidate (distBits:32 | invIdx:20)
                      * every warp lane0: atomicMax(slot,
                        step<<52 | cached) — tag monotonic => stale
                        packets lose, no reset, single slot, exact
                        (val desc, origIdx asc) tie-break
                      * __syncthreads, LDS.64 broadcast -> cur
   blockIdx >= NB : static-copy CTAs for the scale-1.0 rows.
   =================================================================== */
__global__ void __launch_bounds__(TPB, 1) fps_kernel(const float* __restrict__ pos,
                                                     const float* __restrict__ x,
                                                     float* __restrict__ outx,
                                                     float* __restrict__ outp)
{
    /* ------------------- static copy path -------------------------- */
    if (blockIdx.x >= NB) {
        const int  ct  = (int)(blockIdx.x - NB) * TPB + threadIdx.x;
        const int  nth = NCOPY * TPB;
        const float4* x4 = reinterpret_cast<const float4*>(x);
        float4*       o4 = reinterpret_cast<float4*>(outx);
        const int totf4 = NB * NP * (ND / 4);
        for (int idx = ct; idx < totf4; idx += nth) {
            const int row = idx >> 7;
            const int col = idx & 127;
            const int b   = row >> 13;
            const int o   = row & (NP - 1);
            o4[((size_t)(b * ROWS_PER_B + o) << 7) + col] = x4[idx];
        }
        const int totp = NB * NP * 3;
        for (int idx = ct; idx < totp; idx += nth) {
            const int row = idx / 3, c = idx - row * 3;
            const int b = row >> 13, o = row & (NP - 1);
            outp[(size_t)(b * ROWS_PER_B + o) * 3 + c] = pos[idx];
        }
        return;
    }

    /* ------------------------- FPS path ---------------------------- */
    const int b    = blockIdx.x;
    const int tid  = threadIdx.x;
    const int lane = tid & 31;

    extern __shared__ unsigned char smem_raw[];
    unsigned long long* slot = reinterpret_cast<unsigned long long*>(smem_raw + OFF_SLOT);
    int*            scnt  = reinterpret_cast<int*>(smem_raw + OFF_CNT);
    float*          sx    = reinterpret_cast<float*>(smem_raw + OFF_SX);
    float*          sy    = reinterpret_cast<float*>(smem_raw + OFF_SY);
    float*          sz    = reinterpret_cast<float*>(smem_raw + OFF_SZ);
    unsigned*       skey  = reinterpret_cast<unsigned*>(smem_raw + OFF_KEY);
    unsigned short* sid   = reinterpret_cast<unsigned short*>(smem_raw + OFF_SID);

    if (tid == 0) { scnt[0] = 0; scnt[1] = 0; slot[0] = 0ull; }

    const float* pb = pos + (size_t)b * NP * 3;
    for (int i = tid; i < NP; i += TPB) {
        const float px = pb[3 * i + 0];
        const float py = pb[3 * i + 1];
        const float pz = pb[3 * i + 2];
        sx[i] = px; sy[i] = py; sz[i] = pz;
        skey[i] = expand10(quant10(px)) | (expand10(quant10(py)) << 1)
                | (expand10(quant10(pz)) << 2);
        sid[i]  = (unsigned short)i;
    }
    __syncthreads();

    /* bitonic sort (ascending key) of (u32 key, u16 payload) */
    for (int k = 2; k <= NP; k <<= 1) {
        for (int j = k >> 1; j > 0; j >>= 1) {
            for (int i = tid; i < NP; i += TPB) {
                const int ixj = i ^ j;
                if (ixj > i) {
                    const unsigned a = skey[i];
                    const unsigned c = skey[ixj];
                    const bool up = ((i & k) == 0);
                    if ((a > c) == up) {
                        skey[i] = c; skey[ixj] = a;
                        const unsigned short t = sid[i]; sid[i] = sid[ixj]; sid[ixj] = t;
                    }
                }
            }
            __syncthreads();
        }
    }

    /* ownership + permutation validity check (fallback = identity) */
    int ids[PPT];
    int psum = 0, pxor = 0;
#pragma unroll
    for (int kk = 0; kk < PPT; kk++) {
        ids[kk] = (int)sid[tid * PPT + kk];
        psum += ids[kk];
        pxor ^= ids[kk];
    }
    atomicAdd(&scnt[0], psum);
    atomicXor(&scnt[1], pxor);
    __syncthreads();
    const bool perm_ok = (scnt[0] == (NP * (NP - 1) / 2)) && (scnt[1] == 0);
    if (!perm_ok) {
#pragma unroll
        for (int kk = 0; kk < PPT; kk++) ids[kk] = tid * PPT + kk;
    }

    /* 16-element Batcher odd-even mergesort network:
       ids ascending -> strict '>' scan keeps first (lowest) index      */
#define CSWP(a, bb) { if (ids[a] > ids[bb]) { int t = ids[a]; ids[a] = ids[bb]; ids[bb] = t; } }
    CSWP(0,1) CSWP(2,3) CSWP(4,5) CSWP(6,7) CSWP(8,9) CSWP(10,11) CSWP(12,13) CSWP(14,15)
    CSWP(0,2) CSWP(1,3) CSWP(4,6) CSWP(5,7) CSWP(8,10) CSWP(9,11) CSWP(12,14) CSWP(13,15)
    CSWP(1,2) CSWP(5,6) CSWP(9,10) CSWP(13,14)
    CSWP(0,4) CSWP(1,5) CSWP(2,6) CSWP(3,7) CSWP(8,12) CSWP(9,13) CSWP(10,14) CSWP(11,15)
    CSWP(2,4) CSWP(3,5) CSWP(10,12) CSWP(11,13)
    CSWP(1,2) CSWP(3,4) CSWP(5,6) CSWP(9,10) CSWP(11,12) CSWP(13,14)
    CSWP(0,8) CSWP(1,9) CSWP(2,10) CSWP(3,11) CSWP(4,12) CSWP(5,13) CSWP(6,14) CSWP(7,15)
    CSWP(4,8) CSWP(5,9) CSWP(6,10) CSWP(7,11)
    CSWP(2,4) CSWP(3,5) CSWP(6,8) CSWP(7,9) CSWP(10,12) CSWP(11,13)
    CSWP(1,2) CSWP(3,4) CSWP(5,6) CSWP(7,8) CSWP(9,10) CSWP(11,12) CSWP(13,14)
#undef CSWP

    /* owned points -> registers; lane bbox over 16 pts */
    unsigned long long px2[PPT / 2], py2[PPT / 2], pz2[PPT / 2];
    float dist[PPT];
    float bxlo, bxhi, bylo, byhi, bzlo, bzhi;
    {
        float lx0 = sx[ids[0]], ly0 = sy[ids[0]], lz0 = sz[ids[0]];
        bxlo = bxhi = lx0; bylo = byhi = ly0; bzlo = bzhi = lz0;
        float lxp = lx0, lyp = ly0, lzp = lz0;
#pragma unroll
        for (int kk = 0; kk < PPT; kk++) {
            const float lx = sx[ids[kk]], ly = sy[ids[kk]], lz = sz[ids[kk]];
            bxlo = fminf(bxlo, lx); bxhi = fmaxf(bxhi, lx);
            bylo = fminf(bylo, ly); byhi = fmaxf(byhi, ly);
            bzlo = fminf(bzlo, lz); bzhi = fmaxf(bzhi, lz);
            if (kk & 1) {
                px2[kk >> 1] = pack2(lxp, lx);
                py2[kk >> 1] = pack2(lyp, ly);
                pz2[kk >> 1] = pack2(lzp, lz);
            }
            lxp = lx; lyp = ly; lzp = lz;
            dist[kk] = 1e10f;
        }
    }

    float tub = 1e10f;      /* exact max of this thread's dists         */
    /* cached warp candidate, packed [distBits:32 | invIdx:20]          */
    unsigned long long cached = ((unsigned long long)__float_as_uint(1e10f) << 20)
                              | (unsigned)(0xFFFFFu - ids[0]);

    int cur = 0;
    if (tid == 0) g_fps_idx[b * NS1] = 0;

    for (int s = 1; s < NS1; s++) {
        const float cx = sx[cur], cy = sy[cur], cz = sz[cur];    /* LDS bcast */

        /* exact-safe skip test: lower-bound distance from c to lane bbox */
        const float ddx = cx - fminf(fmaxf(cx, bxlo), bxhi);
        const float ddy = cy - fminf(fmaxf(cy, bylo), byhi);
        const float ddz = cz - fminf(fmaxf(cz, bzlo), bzhi);
        const float dmin2 = ddx * ddx + ddy * ddy + ddz * ddz;
        const bool  skip  = (dmin2 * 0.99999f >= tub);

        if (__any_sync(0xffffffffu, !skip)) {
            const unsigned long long ncx = pack2(-cx, -cx);
            const unsigned long long ncy = pack2(-cy, -cy);
            const unsigned long long ncz = pack2(-cz, -cz);
            float best = -1.0f; int bi = ids[0];
#pragma unroll
            for (int kk = 0; kk < PPT / 2; kk++) {
                /* p + (-c) == p - c (RN); separate mul/add roundings == ref */
                const unsigned long long dx = f32x2_add(px2[kk], ncx);
                const unsigned long long dy = f32x2_add(py2[kk], ncy);
                const unsigned long long dz = f32x2_add(pz2[kk], ncz);
                const unsigned long long sm = f32x2_add(
                    f32x2_add(f32x2_mul(dx, dx), f32x2_mul(dy, dy)), f32x2_mul(dz, dz));
                float d0, d1;
                unpack2(sm, d0, d1);
                const float n0 = fminf(dist[2 * kk], d0);     dist[2 * kk] = n0;
                if (n0 > best) { best = n0; bi = ids[2 * kk]; }      /* strict > */
                const float n1 = fminf(dist[2 * kk + 1], d1); dist[2 * kk + 1] = n1;
                if (n1 > best) { best = n1; bi = ids[2 * kk + 1]; }
            }
            tub = best;

            /* warp argmax (dirty warps only): (val desc, id asc) */
            const unsigned vb = __float_as_uint(tub);             /* dist >= 0 */
            const unsigned vm = __reduce_max_sync(0xffffffffu, vb);
            const unsigned iv = __reduce_max_sync(0xffffffffu,
                                  (vb == vm) ? (0xFFFFFu - (unsigned)bi) : 0u);
            cached = ((unsigned long long)vm << 20) | iv;
        }
        /* clean warp: dists unchanged -> cached candidate still exact */

        if (lane == 0)
            atomicMax(slot, ((unsigned long long)s << 52) | cached);
        __syncthreads();

        /* tag s is the max (monotonic) -> slot holds step-s winner */
        const unsigned long long pkt = *((volatile unsigned long long*)slot);
        cur = (int)(0xFFFFFu - ((unsigned)pkt & 0xFFFFFu));

        if (tid == 0) g_fps_idx[b * NS1 + s] = cur;
    }
}

/* ===================================================================
   Gather for SAMPLED rows only (scale 0.5 + 0.25); one 128-thread
   block per row. Scale 0.25 = first 2048 FPS indices (greedy prefix).
   =================================================================== */
__global__ void gather_kernel(const float* __restrict__ x,
                              const float* __restrict__ pos,
                              float* __restrict__ outx,
                              float* __restrict__ outp)
{
    const int r = blockIdx.x;                 /* 0 .. NB*(NS1+NS2)-1 */
    const int b = r / (NS1 + NS2);
    const int o = r - b * (NS1 + NS2);        /* 0 .. 6143           */

    const int src = (o < NS1) ? g_fps_idx[b * NS1 + o]
                              : g_fps_idx[b * NS1 + (o - NS1)];
    const int orow = b * ROWS_PER_B + NP + o;

    const size_t srow = (size_t)b * NP + (size_t)src;
    const float4* xin = reinterpret_cast<const float4*>(x + srow * ND);
    float4*       xo  = reinterpret_cast<float4*>(outx + (size_t)orow * ND);
    xo[threadIdx.x] = xin[threadIdx.x];

    if (threadIdx.x < 3)
        outp[(size_t)orow * 3 + threadIdx.x] = pos[srow * 3 + threadIdx.x];
}

extern "C" void kernel_launch(void* const* d_in, const int* in_sizes, int n_in,
                              void* d_out, int out_size)
{
    const float* x   = (const float*)d_in[0];   /* [B*P, D] f32 */
    const float* pos = (const float*)d_in[1];   /* [B*P, 3] f32 */

    float* outx = (float*)d_out;
    float* outp = outx + OUTX_ELEMS;

    cudaFuncSetAttribute(fps_kernel, cudaFuncAttributeMaxDynamicSharedMemorySize,
                         SMEM_TOTAL);

    fps_kernel<<<NB + NCOPY, TPB, SMEM_TOTAL>>>(pos, x, outx, outp);
    gather_kernel<<<NB * (NS1 + NS2), 128>>>(x, pos, outx, outp);
}

// round 9
// speedup vs baseline: 1.0341x; 1.0341x over previous
#include <cuda_runtime.h>
#include <cstdint>

#define NB 4
#define NP 8192
#define ND 512
#define NS1 4096
#define NS2 2048
#define ROWS_PER_B (NP + NS1 + NS2)   /* 14336 */
#define OUTX_ELEMS ((size_t)NB * ROWS_PER_B * ND)
#define TPB 512                        /* 16 warps -> 4 per SMSP       */
#define PPT 16                         /* points per thread            */
#define NCOPY 144                      /* copy CTAs fused into fps     */

/* smem layout (bytes) */
#define OFF_WCAND 0        /* uint2[64]  = 512           */
#define OFF_CNT   512      /* int ssum, int sxor         */
#define OFF_SX    1024
#define OFF_SY    (OFF_SX + NP * 4)
#define OFF_SZ    (OFF_SY + NP * 4)
#define OFF_KEY   (OFF_SZ + NP * 4)          /* u32[8192] */
#define OFF_SID   (OFF_KEY + NP * 4)         /* u16[8192] */
#define SMEM_TOTAL (OFF_SID + NP * 2)        /* 148480 B  */

__device__ int g_fps_idx[NB * NS1];

/* ---------------- packed f32x2 helpers (proven) -------------------- */
__device__ __forceinline__ unsigned long long f32x2_add(unsigned long long a, unsigned long long b) {
    unsigned long long r;
    asm("add.rn.f32x2 %0, %1, %2;" : "=l"(r) : "l"(a), "l"(b));
    return r;
}
__device__ __forceinline__ unsigned long long f32x2_mul(unsigned long long a, unsigned long long b) {
    unsigned long long r;
    asm("mul.rn.f32x2 %0, %1, %2;" : "=l"(r) : "l"(a), "l"(b));
    return r;
}
__device__ __forceinline__ unsigned long long pack2(float lo, float hi) {
    unsigned long long r;
    asm("mov.b64 %0, {%1, %2};" : "=l"(r) : "f"(lo), "f"(hi));
    return r;
}
__device__ __forceinline__ void unpack2(unsigned long long v, float& lo, float& hi) {
    asm("mov.b64 {%0, %1}, %2;" : "=f"(lo), "=f"(hi) : "l"(v));
}

/* ---------------- Morton helpers ----------------------------------- */
__device__ __forceinline__ unsigned expand10(unsigned v) {
    v &= 0x3FFu;
    v = (v | (v << 16)) & 0x030000FFu;
    v = (v | (v <<  8)) & 0x0300F00Fu;
    v = (v | (v <<  4)) & 0x030C30C3u;
    v = (v | (v <<  2)) & 0x09249249u;
    return v;
}
__device__ __forceinline__ unsigned quant10(float x) {
    float q = (x + 8.0f) * 64.0f;
    q = fminf(fmaxf(q, 0.0f), 1023.0f);
    return (unsigned)q;
}

/* ===================================================================
   Fused kernel.
   blockIdx < NB  : FPS — round-7 structure, but each thread's 16
                    points are split into two Morton-adjacent 8-pt
                    groups with independent AABB / tub / vote / update.
                    Clean warps run the identical round-7 fast path
                    (union box + one vote). Dirty warps usually update
                    only one group (half the issue, shorter chain).
   blockIdx >= NB : static-copy CTAs for the scale-1.0 rows.
   =================================================================== */
__global__ void __launch_bounds__(TPB, 1) fps_kernel(const float* __restrict__ pos,
                                                     const float* __restrict__ x,
                                                     float* __restrict__ outx,
                                                     float* __restrict__ outp)
{
    /* ------------------- static copy path -------------------------- */
    if (blockIdx.x >= NB) {
        const int  ct  = (int)(blockIdx.x - NB) * TPB + threadIdx.x;
        const int  nth = NCOPY * TPB;
        const float4* x4 = reinterpret_cast<const float4*>(x);
        float4*       o4 = reinterpret_cast<float4*>(outx);
        const int totf4 = NB * NP * (ND / 4);
        for (int idx = ct; idx < totf4; idx += nth) {
            const int row = idx >> 7;
            const int col = idx & 127;
            const int b   = row >> 13;
            const int o   = row & (NP - 1);
            o4[((size_t)(b * ROWS_PER_B + o) << 7) + col] = x4[idx];
        }
        const int totp = NB * NP * 3;
        for (int idx = ct; idx < totp; idx += nth) {
            const int row = idx / 3, c = idx - row * 3;
            const int b = row >> 13, o = row & (NP - 1);
            outp[(size_t)(b * ROWS_PER_B + o) * 3 + c] = pos[idx];
        }
        return;
    }

    /* ------------------------- FPS path ---------------------------- */
    const int b    = blockIdx.x;
    const int tid  = threadIdx.x;
    const int lane = tid & 31;
    const int wid  = tid >> 5;

    extern __shared__ unsigned char smem_raw[];
    uint2*          wcand = reinterpret_cast<uint2*>(smem_raw + OFF_WCAND);
    int*            scnt  = reinterpret_cast<int*>(smem_raw + OFF_CNT);
    float*          sx    = reinterpret_cast<float*>(smem_raw + OFF_SX);
    float*          sy    = reinterpret_cast<float*>(smem_raw + OFF_SY);
    float*          sz    = reinterpret_cast<float*>(smem_raw + OFF_SZ);
    unsigned*       skey  = reinterpret_cast<unsigned*>(smem_raw + OFF_KEY);
    unsigned short* sid   = reinterpret_cast<unsigned short*>(smem_raw + OFF_SID);

    if (tid == 0) { scnt[0] = 0; scnt[1] = 0; }

    const float* pb = pos + (size_t)b * NP * 3;
    for (int i = tid; i < NP; i += TPB) {
        const float px = pb[3 * i + 0];
        const float py = pb[3 * i + 1];
        const float pz = pb[3 * i + 2];
        sx[i] = px; sy[i] = py; sz[i] = pz;
        skey[i] = expand10(quant10(px)) | (expand10(quant10(py)) << 1)
                | (expand10(quant10(pz)) << 2);
        sid[i]  = (unsigned short)i;
    }
    __syncthreads();

    /* bitonic sort (ascending key) of (u32 key, u16 payload) */
    for (int k = 2; k <= NP; k <<= 1) {
        for (int j = k >> 1; j > 0; j >>= 1) {
            for (int i = tid; i < NP; i += TPB) {
                const int ixj = i ^ j;
                if (ixj > i) {
                    const unsigned a = skey[i];
                    const unsigned c = skey[ixj];
                    const bool up = ((i & k) == 0);
                    if ((a > c) == up) {
                        skey[i] = c; skey[ixj] = a;
                        const unsigned short t = sid[i]; sid[i] = sid[ixj]; sid[ixj] = t;
                    }
                }
            }
            __syncthreads();
        }
    }

    /* ownership + permutation validity check (fallback = identity) */
    int ids[PPT];
    int psum = 0, pxor = 0;
#pragma unroll
    for (int kk = 0; kk < PPT; kk++) {
        ids[kk] = (int)sid[tid * PPT + kk];
        psum += ids[kk];
        pxor ^= ids[kk];
    }
    atomicAdd(&scnt[0], psum);
    atomicXor(&scnt[1], pxor);
    __syncthreads();
    const bool perm_ok = (scnt[0] == (NP * (NP - 1) / 2)) && (scnt[1] == 0);
    if (!perm_ok) {
#pragma unroll
        for (int kk = 0; kk < PPT; kk++) ids[kk] = tid * PPT + kk;
    }

    /* 16-element Batcher network: ids ascending ->
       group0 = ids[0..7] < group1 = ids[8..15]; strict '>' scans keep
       first (lowest) original index inside each group                  */
#define CSWP(a, bb) { if (ids[a] > ids[bb]) { int t = ids[a]; ids[a] = ids[bb]; ids[bb] = t; } }
    CSWP(0,1) CSWP(2,3) CSWP(4,5) CSWP(6,7) CSWP(8,9) CSWP(10,11) CSWP(12,13) CSWP(14,15)
    CSWP(0,2) CSWP(1,3) CSWP(4,6) CSWP(5,7) CSWP(8,10) CSWP(9,11) CSWP(12,14) CSWP(13,15)
    CSWP(1,2) CSWP(5,6) CSWP(9,10) CSWP(13,14)
    CSWP(0,4) CSWP(1,5) CSWP(2,6) CSWP(3,7) CSWP(8,12) CSWP(9,13) CSWP(10,14) CSWP(11,15)
    CSWP(2,4) CSWP(3,5) CSWP(10,12) CSWP(11,13)
    CSWP(1,2) CSWP(3,4) CSWP(5,6) CSWP(9,10) CSWP(11,12) CSWP(13,14)
    CSWP(0,8) CSWP(1,9) CSWP(2,10) CSWP(3,11) CSWP(4,12) CSWP(5,13) CSWP(6,14) CSWP(7,15)
    CSWP(4,8) CSWP(5,9) CSWP(6,10) CSWP(7,11)
    CSWP(2,4) CSWP(3,5) CSWP(6,8) CSWP(7,9) CSWP(10,12) CSWP(11,13)
    CSWP(1,2) CSWP(3,4) CSWP(5,6) CSWP(7,8) CSWP(9,10) CSWP(11,12) CSWP(13,14)
#undef CSWP

    /* owned points -> registers; per-GROUP (8 pt) bboxes + union box */
    unsigned long long px2[PPT / 2], py2[PPT / 2], pz2[PPT / 2];
    float dist[PPT];
    float g0xlo, g0xhi, g0ylo, g0yhi, g0zlo, g0zhi;
    float g1xlo, g1xhi, g1ylo, g1yhi, g1zlo, g1zhi;
    {
        float lxp = 0.f, lyp = 0.f, lzp = 0.f;
#pragma unroll
        for (int kk = 0; kk < PPT; kk++) {
            const float lx = sx[ids[kk]], ly = sy[ids[kk]], lz = sz[ids[kk]];
            if (kk == 0)      { g0xlo = g0xhi = lx; g0ylo = g0yhi = ly; g0zlo = g0zhi = lz; }
            else if (kk < 8)  { g0xlo = fminf(g0xlo, lx); g0xhi = fmaxf(g0xhi, lx);
                                g0ylo = fminf(g0ylo, ly); g0yhi = fmaxf(g0yhi, ly);
                                g0zlo = fminf(g0zlo, lz); g0zhi = fmaxf(g0zhi, lz); }
            else if (kk == 8) { g1xlo = g1xhi = lx; g1ylo = g1yhi = ly; g1zlo = g1zhi = lz; }
            else              { g1xlo = fminf(g1xlo, lx); g1xhi = fmaxf(g1xhi, lx);
                                g1ylo = fminf(g1ylo, ly); g1yhi = fmaxf(g1yhi, ly);
                                g1zlo = fminf(g1zlo, lz); g1zhi = fmaxf(g1zhi, lz); }
            if (kk & 1) {
                px2[kk >> 1] = pack2(lxp, lx);
                py2[kk >> 1] = pack2(lyp, ly);
                pz2[kk >> 1] = pack2(lzp, lz);
            }
            lxp = lx; lyp = ly; lzp = lz;
            dist[kk] = 1e10f;
        }
    }
    const float uxlo = fminf(g0xlo, g1xlo), uxhi = fmaxf(g0xhi, g1xhi);
    const float uylo = fminf(g0ylo, g1ylo), uyhi = fmaxf(g0yhi, g1yhi);
    const float uzlo = fminf(g0zlo, g1zlo), uzhi = fmaxf(g0zhi, g1zhi);

    float gtub0 = 1e10f, gtub1 = 1e10f;      /* exact per-group max dist  */
    int   gbid0 = ids[0], gbid1 = ids[8];     /* first idx achieving it    */
    /* cached warp candidate (val bits, inv idx) */
    unsigned vm_u = __float_as_uint(1e10f);
    unsigned iv_u = 0xFFFFFu - (unsigned)ids[0];

    int cur = 0;
    if (tid == 0) g_fps_idx[b * NS1] = 0;

    for (int s = 1; s < NS1; s++) {
        const float cx = sx[cur], cy = sy[cur], cz = sz[cur];    /* LDS bcast */

        /* union-box test (same cost as round 7 for clean warps) */
        const float udx = cx - fminf(fmaxf(cx, uxlo), uxhi);
        const float udy = cy - fminf(fmaxf(cy, uylo), uyhi);
        const float udz = cz - fminf(fmaxf(cz, uzlo), uzhi);
        const float udmin2 = udx * udx + udy * udy + udz * udz;
        const float utub   = fmaxf(gtub0, gtub1);
        const bool  udirty = (udmin2 * 0.99999f < utub);

        if (__any_sync(0xffffffffu, udirty)) {
            /* per-group tests (dirty warps only) */
            const float a0x = cx - fminf(fmaxf(cx, g0xlo), g0xhi);
            const float a0y = cy - fminf(fmaxf(cy, g0ylo), g0yhi);
            const float a0z = cz - fminf(fmaxf(cz, g0zlo), g0zhi);
            const float m0  = a0x * a0x + a0y * a0y + a0z * a0z;
            const float a1x = cx - fminf(fmaxf(cx, g1xlo), g1xhi);
            const float a1y = cy - fminf(fmaxf(cy, g1ylo), g1yhi);
            const float a1z = cz - fminf(fmaxf(cz, g1zlo), g1zhi);
            const float m1  = a1x * a1x + a1y * a1y + a1z * a1z;
            const bool d0 = __any_sync(0xffffffffu, m0 * 0.99999f < gtub0);
            const bool d1 = __any_sync(0xffffffffu, m1 * 0.99999f < gtub1);

            const unsigned long long ncx = pack2(-cx, -cx);
            const unsigned long long ncy = pack2(-cy, -cy);
            const unsigned long long ncz = pack2(-cz, -cz);

            if (d0) {   /* update group 0 (pts 0..7); exact arithmetic */
                float best = -1.0f; int bi = ids[0];
#pragma unroll
                for (int kk = 0; kk < 4; kk++) {
                    const unsigned long long dx = f32x2_add(px2[kk], ncx);
                    const unsigned long long dy = f32x2_add(py2[kk], ncy);
                    const unsigned long long dz = f32x2_add(pz2[kk], ncz);
                    const unsigned long long sm = f32x2_add(
                        f32x2_add(f32x2_mul(dx, dx), f32x2_mul(dy, dy)), f32x2_mul(dz, dz));
                    float d0v, d1v;
                    unpack2(sm, d0v, d1v);
                    const float n0 = fminf(dist[2 * kk], d0v);     dist[2 * kk] = n0;
                    if (n0 > best) { best = n0; bi = ids[2 * kk]; }
                    const float n1 = fminf(dist[2 * kk + 1], d1v); dist[2 * kk + 1] = n1;
                    if (n1 > best) { best = n1; bi = ids[2 * kk + 1]; }
                }
                gtub0 = best; gbid0 = bi;
            }
            if (d1) {   /* update group 1 (pts 8..15) */
                float best = -1.0f; int bi = ids[8];
#pragma unroll
                for (int kk = 4; kk < 8; kk++) {
                    const unsigned long long dx = f32x2_add(px2[kk], ncx);
                    const unsigned long long dy = f32x2_add(py2[kk], ncy);
                    const unsigned long long dz = f32x2_add(pz2[kk], ncz);
                    const unsigned long long sm = f32x2_add(
                        f32x2_add(f32x2_mul(dx, dx), f32x2_mul(dy, dy)), f32x2_mul(dz, dz));
                    float d0v, d1v;
                    unpack2(sm, d0v, d1v);
                    const float n0 = fminf(dist[2 * kk], d0v);     dist[2 * kk] = n0;
                    if (n0 > best) { best = n0; bi = ids[2 * kk]; }
                    const float n1 = fminf(dist[2 * kk + 1], d1v); dist[2 * kk + 1] = n1;
                    if (n1 > best) { best = n1; bi = ids[2 * kk + 1]; }
                }
                gtub1 = best; gbid1 = bi;
            }

            if (d0 | d1) {
                /* thread candidate: group0 ids < group1 ids, so >= on
                   values picks the FIRST index on ties */
                const float tub = fmaxf(gtub0, gtub1);
                const int   bid = (gtub0 >= gtub1) ? gbid0 : gbid1;
                const unsigned vb = __float_as_uint(tub);         /* dist >= 0 */
                vm_u = __reduce_max_sync(0xffffffffu, vb);
                iv_u = __reduce_max_sync(0xffffffffu,
                           (vb == vm_u) ? (0xFFFFFu - (unsigned)bid) : 0u);
            }
        }
        /* clean warp (any tier): no lane's dists changed ->
           cached (vm_u, iv_u) still the exact warp candidate */

        const int sl = s & 1;
        if (lane == 0) wcand[(sl << 4) + wid] = make_uint2(vm_u, iv_u);
        __syncthreads();

        /* every warp redundantly reduces the 16 warp candidates */
        const uint2 wc = (lane < 16) ? wcand[(sl << 4) + lane] : make_uint2(0u, 0u);
        const unsigned vm2 = __reduce_max_sync(0xffffffffu, wc.x);
        const unsigned iv2 = __reduce_max_sync(0xffffffffu,
                               (wc.x == vm2) ? wc.y : 0u);
        cur = (int)(0xFFFFFu - iv2);

        if (tid == 0) g_fps_idx[b * NS1 + s] = cur;
    }
}

/* ===================================================================
   Gather for SAMPLED rows only (scale 0.5 + 0.25); one 128-thread
   block per row. Scale 0.25 = first 2048 FPS indices (greedy prefix).
   =================================================================== */
__global__ void gather_kernel(const float* __restrict__ x,
                              const float* __restrict__ pos,
                              float* __restrict__ outx,
                              float* __restrict__ outp)
{
    const int r = blockIdx.x;                 /* 0 .. NB*(NS1+NS2)-1 */
    const int b = r / (NS1 + NS2);
    const int o = r - b * (NS1 + NS2);        /* 0 .. 6143           */

    const int src = (o < NS1) ? g_fps_idx[b * NS1 + o]
                              : g_fps_idx[b * NS1 + (o - NS1)];
    const int orow = b * ROWS_PER_B + NP + o;

    const size_t srow = (size_t)b * NP + (size_t)src;
    const float4* xin = reinterpret_cast<const float4*>(x + srow * ND);
    float4*       xo  = reinterpret_cast<float4*>(outx + (size_t)orow * ND);
    xo[threadIdx.x] = xin[threadIdx.x];

    if (threadIdx.x < 3)
        outp[(size_t)orow * 3 + threadIdx.x] = pos[srow * 3 + threadIdx.x];
}

extern "C" void kernel_launch(void* const* d_in, const int* in_sizes, int n_in,
                              void* d_out, int out_size)
{
    const float* x   = (const float*)d_in[0];   /* [B*P, D] f32 */
    const float* pos = (const float*)d_in[1];   /* [B*P, 3] f32 */

    float* outx = (float*)d_out;
    float* outp = outx + OUTX_ELEMS;

    cudaFuncSetAttribute(fps_kernel, cudaFuncAttributeMaxDynamicSharedMemorySize,
                         SMEM_TOTAL);

    fps_kernel<<<NB + NCOPY, TPB, SMEM_TOTAL>>>(pos, x, outx, outp);
    gather_kernel<<<NB * (NS1 + NS2), 128>>>(x, pos, outx, outp);
}

// round 10
// speedup vs baseline: 1.2631x; 1.2215x over previous
#include <cuda_runtime.h>
#include <cstdint>

#define NB 4
#define NP 8192
#define ND 512
#define NS1 4096
#define NS2 2048
#define ROWS_PER_B (NP + NS1 + NS2)   /* 14336 */
#define OUTX_ELEMS ((size_t)NB * ROWS_PER_B * ND)
#define TPB 512                        /* 16 warps -> 4 per SMSP       */
#define PPT 16                         /* points per thread            */
#define NCOPY 144                      /* copy CTAs fused into fps     */

/* smem layout (bytes) */
#define OFF_WCAND 0        /* uint2[64]  = 512            */
#define OFF_CNT   512      /* int ssum, int sxor          */
#define OFF_POS   1024                         /* float4[8192] = 131072 */
#define OFF_KEY   (OFF_POS + NP * 16)          /* u32[8192]; reused as
                                                  int sidx[NS1] in loop */
#define OFF_SID   (OFF_KEY + NP * 4)           /* u16[8192]             */
#define SMEM_TOTAL (OFF_SID + NP * 2)          /* 181248 B              */

__device__ int g_fps_idx[NB * NS1];

/* ---------------- packed f32x2 helpers (proven) -------------------- */
__device__ __forceinline__ unsigned long long f32x2_add(unsigned long long a, unsigned long long b) {
    unsigned long long r;
    asm("add.rn.f32x2 %0, %1, %2;" : "=l"(r) : "l"(a), "l"(b));
    return r;
}
__device__ __forceinline__ unsigned long long f32x2_mul(unsigned long long a, unsigned long long b) {
    unsigned long long r;
    asm("mul.rn.f32x2 %0, %1, %2;" : "=l"(r) : "l"(a), "l"(b));
    return r;
}
__device__ __forceinline__ unsigned long long pack2(float lo, float hi) {
    unsigned long long r;
    asm("mov.b64 %0, {%1, %2};" : "=l"(r) : "f"(lo), "f"(hi));
    return r;
}
__device__ __forceinline__ void unpack2(unsigned long long v, float& lo, float& hi) {
    asm("mov.b64 {%0, %1}, %2;" : "=f"(lo), "=f"(hi) : "l"(v));
}

/* ---------------- Morton helpers ----------------------------------- */
__device__ __forceinline__ unsigned expand10(unsigned v) {
    v &= 0x3FFu;
    v = (v | (v << 16)) & 0x030000FFu;
    v = (v | (v <<  8)) & 0x0300F00Fu;
    v = (v | (v <<  4)) & 0x030C30C3u;
    v = (v | (v <<  2)) & 0x09249249u;
    return v;
}
__device__ __forceinline__ unsigned quant10(float x) {
    float q = (x + 8.0f) * 64.0f;
    q = fminf(fmaxf(q, 0.0f), 1023.0f);
    return (unsigned)q;
}

/* ===================================================================
   Fused kernel.
   blockIdx < NB  : FPS — round-7 hot loop with three chain-only
                    micro-cuts: float4 centroid LDS.128, per-step index
                    store to SMEM (global dump after the loop), and
                    parity constant-folding via unroll 2.
   blockIdx >= NB : static-copy CTAs for the scale-1.0 rows.
   =================================================================== */
__global__ void __launch_bounds__(TPB, 1) fps_kernel(const float* __restrict__ pos,
                                                     const float* __restrict__ x,
                                                     float* __restrict__ outx,
                                                     float* __restrict__ outp)
{
    /* ------------------- static copy path -------------------------- */
    if (blockIdx.x >= NB) {
        const int  ct  = (int)(blockIdx.x - NB) * TPB + threadIdx.x;
        const int  nth = NCOPY * TPB;
        const float4* x4 = reinterpret_cast<const float4*>(x);
        float4*       o4 = reinterpret_cast<float4*>(outx);
        const int totf4 = NB * NP * (ND / 4);
        for (int idx = ct; idx < totf4; idx += nth) {
            const int row = idx >> 7;
            const int col = idx & 127;
            const int b   = row >> 13;
            const int o   = row & (NP - 1);
            o4[((size_t)(b * ROWS_PER_B + o) << 7) + col] = x4[idx];
        }
        const int totp = NB * NP * 3;
        for (int idx = ct; idx < totp; idx += nth) {
            const int row = idx / 3, c = idx - row * 3;
            const int b = row >> 13, o = row & (NP - 1);
            outp[(size_t)(b * ROWS_PER_B + o) * 3 + c] = pos[idx];
        }
        return;
    }

    /* ------------------------- FPS path ---------------------------- */
    const int b    = blockIdx.x;
    const int tid  = threadIdx.x;
    const int lane = tid & 31;
    const int wid  = tid >> 5;

    extern __shared__ unsigned char smem_raw[];
    uint2*          wcand = reinterpret_cast<uint2*>(smem_raw + OFF_WCAND);
    int*            scnt  = reinterpret_cast<int*>(smem_raw + OFF_CNT);
    float4*         spos  = reinterpret_cast<float4*>(smem_raw + OFF_POS);
    unsigned*       skey  = reinterpret_cast<unsigned*>(smem_raw + OFF_KEY);
    int*            sidx  = reinterpret_cast<int*>(smem_raw + OFF_KEY);  /* reuse post-sort */
    unsigned short* sid   = reinterpret_cast<unsigned short*>(smem_raw + OFF_SID);

    if (tid == 0) { scnt[0] = 0; scnt[1] = 0; }

    const float* pb = pos + (size_t)b * NP * 3;
    for (int i = tid; i < NP; i += TPB) {
        const float px = pb[3 * i + 0];
        const float py = pb[3 * i + 1];
        const float pz = pb[3 * i + 2];
        spos[i] = make_float4(px, py, pz, 0.0f);
        skey[i] = expand10(quant10(px)) | (expand10(quant10(py)) << 1)
                | (expand10(quant10(pz)) << 2);
        sid[i]  = (unsigned short)i;
    }
    __syncthreads();

    /* bitonic sort (ascending key) of (u32 key, u16 payload) */
    for (int k = 2; k <= NP; k <<= 1) {
        for (int j = k >> 1; j > 0; j >>= 1) {
            for (int i = tid; i < NP; i += TPB) {
                const int ixj = i ^ j;
                if (ixj > i) {
                    const unsigned a = skey[i];
                    const unsigned c = skey[ixj];
                    const bool up = ((i & k) == 0);
                    if ((a > c) == up) {
                        skey[i] = c; skey[ixj] = a;
                        const unsigned short t = sid[i]; sid[i] = sid[ixj]; sid[ixj] = t;
                    }
                }
            }
            __syncthreads();
        }
    }

    /* ownership + permutation validity check (fallback = identity) */
    int ids[PPT];
    int psum = 0, pxor = 0;
#pragma unroll
    for (int kk = 0; kk < PPT; kk++) {
        ids[kk] = (int)sid[tid * PPT + kk];
        psum += ids[kk];
        pxor ^= ids[kk];
    }
    atomicAdd(&scnt[0], psum);
    atomicXor(&scnt[1], pxor);
    __syncthreads();
    const bool perm_ok = (scnt[0] == (NP * (NP - 1) / 2)) && (scnt[1] == 0);
    if (!perm_ok) {
#pragma unroll
        for (int kk = 0; kk < PPT; kk++) ids[kk] = tid * PPT + kk;
    }

    /* 16-element Batcher odd-even mergesort network:
       ids ascending -> strict '>' scan keeps first (lowest) index      */
#define CSWP(a, bb) { if (ids[a] > ids[bb]) { int t = ids[a]; ids[a] = ids[bb]; ids[bb] = t; } }
    CSWP(0,1) CSWP(2,3) CSWP(4,5) CSWP(6,7) CSWP(8,9) CSWP(10,11) CSWP(12,13) CSWP(14,15)
    CSWP(0,2) CSWP(1,3) CSWP(4,6) CSWP(5,7) CSWP(8,10) CSWP(9,11) CSWP(12,14) CSWP(13,15)
    CSWP(1,2) CSWP(5,6) CSWP(9,10) CSWP(13,14)
    CSWP(0,4) CSWP(1,5) CSWP(2,6) CSWP(3,7) CSWP(8,12) CSWP(9,13) CSWP(10,14) CSWP(11,15)
    CSWP(2,4) CSWP(3,5) CSWP(10,12) CSWP(11,13)
    CSWP(1,2) CSWP(3,4) CSWP(5,6) CSWP(9,10) CSWP(11,12) CSWP(13,14)
    CSWP(0,8) CSWP(1,9) CSWP(2,10) CSWP(3,11) CSWP(4,12) CSWP(5,13) CSWP(6,14) CSWP(7,15)
    CSWP(4,8) CSWP(5,9) CSWP(6,10) CSWP(7,11)
    CSWP(2,4) CSWP(3,5) CSWP(6,8) CSWP(7,9) CSWP(10,12) CSWP(11,13)
    CSWP(1,2) CSWP(3,4) CSWP(5,6) CSWP(7,8) CSWP(9,10) CSWP(11,12) CSWP(13,14)
#undef CSWP
    __syncthreads();      /* sid/skey fully consumed; skey becomes sidx */

    /* owned points -> registers; lane bbox over 16 pts */
    unsigned long long px2[PPT / 2], py2[PPT / 2], pz2[PPT / 2];
    float dist[PPT];
    float bxlo, bxhi, bylo, byhi, bzlo, bzhi;
    {
        const float4 p0 = spos[ids[0]];
        bxlo = bxhi = p0.x; bylo = byhi = p0.y; bzlo = bzhi = p0.z;
        float lxp = p0.x, lyp = p0.y, lzp = p0.z;
#pragma unroll
        for (int kk = 0; kk < PPT; kk++) {
            const float4 p = spos[ids[kk]];
            bxlo = fminf(bxlo, p.x); bxhi = fmaxf(bxhi, p.x);
            bylo = fminf(bylo, p.y); byhi = fmaxf(byhi, p.y);
            bzlo = fminf(bzlo, p.z); bzhi = fmaxf(bzhi, p.z);
            if (kk & 1) {
                px2[kk >> 1] = pack2(lxp, p.x);
                py2[kk >> 1] = pack2(lyp, p.y);
                pz2[kk >> 1] = pack2(lzp, p.z);
            }
            lxp = p.x; lyp = p.y; lzp = p.z;
            dist[kk] = 1e10f;
        }
    }

    float tub  = 1e10f;    /* exact max of this thread's dists          */
    int   tbid = ids[0];   /* first original index achieving that max   */

    int cur = 0;
    if (tid == 0) sidx[0] = 0;

#pragma unroll 2
    for (int s = 1; s < NS1; s++) {
        const float4 c4 = spos[cur];                    /* one LDS.128 bcast */
        const float cx = c4.x, cy = c4.y, cz = c4.z;

        /* exact-safe skip test: lower-bound distance from c to lane bbox */
        const float ddx = cx - fminf(fmaxf(cx, bxlo), bxhi);
        const float ddy = cy - fminf(fmaxf(cy, bylo), byhi);
        const float ddz = cz - fminf(fmaxf(cz, bzlo), bzhi);
        const float dmin2 = ddx * ddx + ddy * ddy + ddz * ddz;
        const bool  skip  = (dmin2 * 0.99999f >= tub);

        if (__any_sync(0xffffffffu, !skip)) {
            const unsigned long long ncx = pack2(-cx, -cx);
            const unsigned long long ncy = pack2(-cy, -cy);
            const unsigned long long ncz = pack2(-cz, -cz);
            float best = -1.0f; int bi = ids[0];
#pragma unroll
            for (int kk = 0; kk < PPT / 2; kk++) {
                /* p + (-c) == p - c (RN); separate mul/add roundings == ref */
                const unsigned long long dx = f32x2_add(px2[kk], ncx);
                const unsigned long long dy = f32x2_add(py2[kk], ncy);
                const unsigned long long dz = f32x2_add(pz2[kk], ncz);
                const unsigned long long sm = f32x2_add(
                    f32x2_add(f32x2_mul(dx, dx), f32x2_mul(dy, dy)), f32x2_mul(dz, dz));
                float d0, d1;
                unpack2(sm, d0, d1);
                const float n0 = fminf(dist[2 * kk], d0);     dist[2 * kk] = n0;
                if (n0 > best) { best = n0; bi = ids[2 * kk]; }      /* strict > */
                const float n1 = fminf(dist[2 * kk + 1], d1); dist[2 * kk + 1] = n1;
                if (n1 > best) { best = n1; bi = ids[2 * kk + 1]; }
            }
            tub = best; tbid = bi;
        }
        /* skip-step: dists provably unchanged -> (tub, tbid) still exact */

        /* warp argmax every step: (val desc, id asc) */
        const unsigned vb = __float_as_uint(tub);                 /* dist >= 0 */
        const unsigned vm = __reduce_max_sync(0xffffffffu, vb);
        const unsigned im = __reduce_min_sync(0xffffffffu,
                              (vb == vm) ? (unsigned)tbid : 0xFFFFFFFFu);
        const int sl = s & 1;
        if (lane == 0) wcand[(sl << 4) + wid] = make_uint2(vm, im);
        __syncthreads();

        /* every warp redundantly reduces the 16 warp candidates */
        const uint2 wc = (lane < 16) ? wcand[(sl << 4) + lane] : make_uint2(0u, 0u);
        const unsigned vm2 = __reduce_max_sync(0xffffffffu, wc.x);
        const unsigned im2 = __reduce_min_sync(0xffffffffu,
                               (wc.x == vm2) ? wc.y : 0xFFFFFFFFu);
        cur = (int)im2;

        if (tid == 0) sidx[s] = cur;        /* STS, not STG: off-chain */
    }
    __syncthreads();

    /* coalesced index dump */
    for (int i = tid; i < NS1; i += TPB)
        g_fps_idx[b * NS1 + i] = sidx[i];
}

/* ===================================================================
   Gather for SAMPLED rows only (scale 0.5 + 0.25); one 128-thread
   block per row. Scale 0.25 = first 2048 FPS indices (greedy prefix).
   =================================================================== */
__global__ void gather_kernel(const float* __restrict__ x,
                              const float* __restrict__ pos,
                              float* __restrict__ outx,
                              float* __restrict__ outp)
{
    const int r = blockIdx.x;                 /* 0 .. NB*(NS1+NS2)-1 */
    const int b = r / (NS1 + NS2);
    const int o = r - b * (NS1 + NS2);        /* 0 .. 6143           */

    const int src = (o < NS1) ? g_fps_idx[b * NS1 + o]
                              : g_fps_idx[b * NS1 + (o - NS1)];
    const int orow = b * ROWS_PER_B + NP + o;

    const size_t srow = (size_t)b * NP + (size_t)src;
    const float4* xin = reinterpret_cast<const float4*>(x + srow * ND);
    float4*       xo  = reinterpret_cast<float4*>(outx + (size_t)orow * ND);
    xo[threadIdx.x] = xin[threadIdx.x];

    if (threadIdx.x < 3)
        outp[(size_t)orow * 3 + threadIdx.x] = pos[srow * 3 + threadIdx.x];
}

extern "C" void kernel_launch(void* const* d_in, const int* in_sizes, int n_in,
                              void* d_out, int out_size)
{
    const float* x   = (const float*)d_in[0];   /* [B*P, D] f32 */
    const float* pos = (const float*)d_in[1];   /* [B*P, 3] f32 */

    float* outx = (float*)d_out;
    float* outp = outx + OUTX_ELEMS;

    cudaFuncSetAttribute(fps_kernel, cudaFuncAttributeMaxDynamicSharedMemorySize,
                         SMEM_TOTAL);

    fps_kernel<<<NB + NCOPY, TPB, SMEM_TOTAL>>>(pos, x, outx, outp);
    gather_kernel<<<NB * (NS1 + NS2), 128>>>(x, pos, outx, outp);
}